// round 17
// baseline (speedup 1.0000x reference)
#include <cuda_runtime.h>
#include <cuda_fp16.h>
#include <mma.h>
#include <math.h>
#include <stdint.h>

using namespace nvcuda;

#define B_ 8
#define T_ 128
#define S_ 256
#define H_ 512

// scratch
__device__ float  g_qs[B_ * T_ * H_];                // 2 MB  qs fp32
__device__ __half g_hsh[B_ * S_ * H_];               // 2 MB  hs fp16
__device__ float  g_po[4][B_ * T_ * H_];             // 8 MB  out split-K partials
// fp16 operands
__device__ __half g_qf16[B_ * T_ * H_];              // 1 MB
__device__ __half g_ef16[B_ * S_ * H_];              // 2 MB
__device__ __half g_wsf16[H_ * H_];                  // 0.5 MB
__device__ __half g_whf16[H_ * H_];                  // 0.5 MB
__device__ __half g_wof16[H_ * 2 * H_];              // 1 MB
__device__ __half g_cf16[B_ * T_ * H_];              // 1 MB  ctx fp16

// ---------------------------------------------------------------------------
__device__ __forceinline__ uint32_t smem_u32(const void* p) {
    uint32_t a;
    asm("{ .reg .u64 t; cvta.to.shared.u64 t, %1; cvt.u32.u64 %0, t; }"
        : "=r"(a) : "l"(p));
    return a;
}
__device__ __forceinline__ void cpa16(uint32_t d, const void* s) {
    asm volatile("cp.async.cg.shared.global [%0], [%1], 16;" :: "r"(d), "l"(s));
}
#define CP_COMMIT() asm volatile("cp.async.commit_group;" ::: "memory")
#define CP_WAIT1()  asm volatile("cp.async.wait_group 1;" ::: "memory")
#define CP_WAIT0()  asm volatile("cp.async.wait_group 0;" ::: "memory")

__device__ __forceinline__ __half2 tanh2(__half2 x) {
    __half2 r;
    asm("tanh.approx.f16x2 %0, %1;"
        : "=r"(*reinterpret_cast<uint32_t*>(&r))
        : "r"(*reinterpret_cast<const uint32_t*>(&x)));
    return r;
}
__device__ __forceinline__ uint2 pack_f16x4(float x, float y, float z, float w) {
    const __half2 h0 = __floats2half2_rn(x, y);
    const __half2 h1 = __floats2half2_rn(z, w);
    uint2 st;
    st.x = *reinterpret_cast<const uint32_t*>(&h0);
    st.y = *reinterpret_cast<const uint32_t*>(&h1);
    return st;
}

// ---------------------------------------------------------------------------
// convert: everything to fp16. One float4 per thread.
// ---------------------------------------------------------------------------
__global__ void __launch_bounds__(256) convert_kernel(
    const float* __restrict__ query, const float* __restrict__ enc,
    const float* __restrict__ W_s, const float* __restrict__ W_h,
    const float* __restrict__ W_out)
{
    const int i4 = blockIdx.x * 256 + threadIdx.x;
    const float* src;
    __half* dst;
    int off;
    if (i4 < 131072)      { src = query; dst = g_qf16;  off = i4; }
    else if (i4 < 393216) { src = enc;   dst = g_ef16;  off = i4 - 131072; }
    else if (i4 < 458752) { src = W_s;   dst = g_wsf16; off = i4 - 393216; }
    else if (i4 < 524288) { src = W_h;   dst = g_whf16; off = i4 - 458752; }
    else                  { src = W_out; dst = g_wof16; off = i4 - 524288; }

    const float4 v = reinterpret_cast<const float4*>(src)[off];
    reinterpret_cast<uint2*>(dst)[off] = pack_f16x4(v.x, v.y, v.z, v.w);
}

// ---------------------------------------------------------------------------
// fp16 single-product wmma GEMM, 3-stage cp.async pipeline.
// Tile 64x64, 256 threads, 8 warps (warp tile 16x32), K-chunk 32.
// F16OUT: epilogue converts to fp16 (pitch H_); else fp32 direct store.
// ---------------------------------------------------------------------------
#define FPITCH 40                           // halves; 80 B per row
#define FTILE_B (64 * FPITCH * 2)           // 5120 B per tile
#define FA_O 0
#define FB_O (FTILE_B)
#define FBUF_B (2 * FTILE_B)                // 10240 B per stage
#define FSMEM_BYTES (3 * FBUF_B)            // 30720 B (>= 16KB f32 stage)

__device__ __forceinline__ void issue_chunk_f16(
    uint32_t sb,
    const __half* __restrict__ A, const __half* __restrict__ Bw,
    int ldb, int m0, int n0, int ak, int bk, int tid)
{
    const int row = tid >> 2, seg = tid & 3;           // 64 rows x 4 x 16B
    const uint32_t soff = (uint32_t)(row * (FPITCH * 2) + seg * 16);
    cpa16(sb + FA_O + soff, A + (size_t)(m0 + row) * H_ + ak + seg * 8);
    cpa16(sb + FB_O + soff, Bw + (size_t)(n0 + row) * ldb + bk + seg * 8);
}

template <bool F16OUT>
__device__ __forceinline__ void gemm_f16(
    char* smem,
    const __half* __restrict__ A, const __half* __restrict__ Bw,
    int ldb, float* __restrict__ Cf32, __half* __restrict__ Cf16,
    int m0, int n0, int akbeg, int bkbeg, int nchunks)
{
    const int tid  = threadIdx.x;
    const int wid  = tid >> 5;
    const int m0w  = (wid >> 1) * 16;
    const int n0w  = (wid & 1) * 32;
    const uint32_t sb = smem_u32(smem);

    wmma::fragment<wmma::accumulator, 16, 16, 16, float> acc[2];
    wmma::fill_fragment(acc[0], 0.0f);
    wmma::fill_fragment(acc[1], 0.0f);

    // prologue: 2 chunks in flight
    issue_chunk_f16(sb, A, Bw, ldb, m0, n0, akbeg, bkbeg, tid);
    CP_COMMIT();
    if (nchunks > 1) {
        issue_chunk_f16(sb + FBUF_B, A, Bw, ldb, m0, n0,
                        akbeg + 32, bkbeg + 32, tid);
        CP_COMMIT();
    }

    int buf = 0;
    #pragma unroll 1
    for (int it = 0; it < nchunks; ++it) {
        if (it + 1 < nchunks) CP_WAIT1(); else CP_WAIT0();
        __syncthreads();   // chunk `it` resident in buffer `buf`; all warps done
                           // reading buffer (buf+1)%3's previous contents

        // issue chunk it+2 into buffer (buf+2)%3 (freed by prior iteration)
        if (it + 2 < nchunks) {
            int nb = buf + 2; if (nb >= 3) nb -= 3;
            issue_chunk_f16(sb + nb * FBUF_B, A, Bw, ldb, m0, n0,
                            akbeg + (it + 2) * 32, bkbeg + (it + 2) * 32, tid);
            CP_COMMIT();
        }

        const char* bufp = smem + buf * FBUF_B;
        const __half* sA = reinterpret_cast<const __half*>(bufp + FA_O);
        const __half* sB = reinterpret_cast<const __half*>(bufp + FB_O);

        #pragma unroll
        for (int kf = 0; kf < 2; kf++) {
            const int ko = kf * 16;
            wmma::fragment<wmma::matrix_a, 16, 16, 16, __half, wmma::row_major> af;
            wmma::fragment<wmma::matrix_b, 16, 16, 16, __half, wmma::col_major> bf[2];
            wmma::load_matrix_sync(af, &sA[m0w * FPITCH + ko], FPITCH);
            #pragma unroll
            for (int ni = 0; ni < 2; ni++)
                wmma::load_matrix_sync(bf[ni], &sB[(n0w + 16 * ni) * FPITCH + ko], FPITCH);
            #pragma unroll
            for (int ni = 0; ni < 2; ni++)
                wmma::mma_sync(acc[ni], af, bf[ni], acc[ni]);
        }
        __syncthreads();   // all warps done reading buffer `buf`
        if (++buf == 3) buf = 0;
    }

    if (!F16OUT) {
        #pragma unroll
        for (int ni = 0; ni < 2; ni++)
            wmma::store_matrix_sync(
                &Cf32[(size_t)(m0 + m0w) * H_ + n0 + n0w + 16 * ni],
                acc[ni], H_, wmma::mem_row_major);
    } else {
        // stage fp32 in smem (16 KB < 30 KB pipeline smem), then convert
        float* stage = reinterpret_cast<float*>(smem);
        #pragma unroll
        for (int ni = 0; ni < 2; ni++)
            wmma::store_matrix_sync(&stage[m0w * 64 + n0w + 16 * ni],
                                    acc[ni], 64, wmma::mem_row_major);
        __syncthreads();
        const int row = tid >> 2;
        const int cq  = (tid & 3) * 16;
        const float4 s0 = *reinterpret_cast<const float4*>(&stage[row * 64 + cq + 0]);
        const float4 s1 = *reinterpret_cast<const float4*>(&stage[row * 64 + cq + 4]);
        const float4 s2 = *reinterpret_cast<const float4*>(&stage[row * 64 + cq + 8]);
        const float4 s3 = *reinterpret_cast<const float4*>(&stage[row * 64 + cq + 12]);
        __half* drow = Cf16 + (size_t)(m0 + row) * H_ + n0 + cq;
        uint4 o0, o1;
        *reinterpret_cast<uint2*>(&o0.x) = pack_f16x4(s0.x, s0.y, s0.z, s0.w);
        *reinterpret_cast<uint2*>(&o0.z) = pack_f16x4(s1.x, s1.y, s1.z, s1.w);
        *reinterpret_cast<uint2*>(&o1.x) = pack_f16x4(s2.x, s2.y, s2.z, s2.w);
        *reinterpret_cast<uint2*>(&o1.z) = pack_f16x4(s3.x, s3.y, s3.z, s3.w);
        *reinterpret_cast<uint4*>(drow) = o0;
        *reinterpret_cast<uint4*>(drow + 8) = o1;
    }
}

// proj: grid (8, 48). y<16 -> qs fp32 (full K); else hs fp16 (full K).
__global__ void __launch_bounds__(256) proj_f16()
{
    __shared__ __align__(16) char smem[FSMEM_BYTES];
    const int n0 = blockIdx.x * 64;
    const int my = blockIdx.y;
    if (my < 16)
        gemm_f16<false>(smem, g_qf16, g_wsf16, H_, g_qs, nullptr,
                        my * 64, n0, 0, 0, 16);
    else
        gemm_f16<true>(smem, g_ef16, g_whf16, H_, nullptr, g_hsh,
                       (my - 16) * 64, n0, 0, 0, 16);
}

// out: grid (8, 16, 4). kz<2 reads ctx f16, kz>=2 reads query f16.
__global__ void __launch_bounds__(256) out_f16()
{
    __shared__ __align__(16) char smem[FSMEM_BYTES];
    const int kz = blockIdx.z;
    const __half* A = (kz < 2) ? g_cf16 : g_qf16;
    gemm_f16<false>(smem, A, g_wof16, 2 * H_, g_po[kz], nullptr,
                    blockIdx.y * 64, blockIdx.x * 64,
                    (kz & 1) * 256, kz * 256, 8);
}

// oreduce: out = tanh(p0+p1+p2+p3 + bias)  (131072 float4s -> 512 blocks)
__global__ void __launch_bounds__(256) oreduce_kernel(
    const float* __restrict__ bias, float* __restrict__ out)
{
    const int i4 = blockIdx.x * 256 + threadIdx.x;
    const float4 p0 = reinterpret_cast<const float4*>(g_po[0])[i4];
    const float4 p1 = reinterpret_cast<const float4*>(g_po[1])[i4];
    const float4 p2 = reinterpret_cast<const float4*>(g_po[2])[i4];
    const float4 p3 = reinterpret_cast<const float4*>(g_po[3])[i4];
    const float4 bb = *reinterpret_cast<const float4*>(&bias[(i4 & 127) * 4]);
    float4 o;
    o.x = tanhf(p0.x + p1.x + p2.x + p3.x + bb.x);
    o.y = tanhf(p0.y + p1.y + p2.y + p3.y + bb.y);
    o.z = tanhf(p0.z + p1.z + p2.z + p3.z + bb.z);
    o.w = tanhf(p0.w + p1.w + p2.w + p3.w + bb.w);
    reinterpret_cast<float4*>(out)[i4] = o;
}

// ---------------------------------------------------------------------------
// Fused attention, TT=4, 512 threads, 256 blocks, 2 CTAs/SM. (unchanged)
// ---------------------------------------------------------------------------
#define TT 4
#define SC 16

__global__ void __launch_bounds__(512, 2) attn_kernel(
    const float* __restrict__ enc, const float* __restrict__ v,
    const int* __restrict__ lens)
{
    __shared__ __align__(16) __half sh_hs[2][SC * H_];   // 2 x 16 KB
    __shared__ float sh_sc[S_][TT];                      // 4 KB (transposed)
    __shared__ float sh_rsum[TT];

    const int b     = blockIdx.y;
    const int t0    = blockIdx.x * TT;
    const int tid   = threadIdx.x;
    const int lane  = tid & 31;
    const int wid   = tid >> 5;
    const int t_loc = wid >> 2;
    const int squad = wid & 3;

    const int len = lens[b];
    const int nch = (len + SC - 1) / SC;

    __half2 qh[8], vh[8];
    {
        const size_t ro = (size_t)(b * T_ + t0 + t_loc) * H_;
        #pragma unroll
        for (int c = 0; c < 2; c++) {
            #pragma unroll
            for (int k2 = 0; k2 < 2; k2++) {
                const int off = c * 256 + lane * 8 + k2 * 4;
                const float4 p0 = *reinterpret_cast<const float4*>(&g_qs[ro + off]);
                const float4 vv = *reinterpret_cast<const float4*>(&v[off]);
                qh[c * 4 + k2 * 2 + 0] = __floats2half2_rn(p0.x, p0.y);
                qh[c * 4 + k2 * 2 + 1] = __floats2half2_rn(p0.z, p0.w);
                vh[c * 4 + k2 * 2 + 0] = __floats2half2_rn(vv.x, vv.y);
                vh[c * 4 + k2 * 2 + 1] = __floats2half2_rn(vv.z, vv.w);
            }
        }
    }

    const __half* hsb = g_hsh + (size_t)b * S_ * H_;
    const float* encb = enc + (size_t)b * S_ * H_;

    uint4 r[2];
    #pragma unroll
    for (int q = 0; q < 2; q++)
        r[q] = reinterpret_cast<const uint4*>(hsb)[q * 512 + tid];
    #pragma unroll
    for (int q = 0; q < 2; q++)
        reinterpret_cast<uint4*>(&sh_hs[0][0])[q * 512 + tid] = r[q];

    #pragma unroll 1
    for (int it = 0; it < nch; ++it) {
        if (it + 1 < nch) {
            const uint4* nxt = reinterpret_cast<const uint4*>(hsb + (size_t)(it + 1) * SC * H_);
            #pragma unroll
            for (int q = 0; q < 2; q++)
                r[q] = nxt[q * 512 + tid];
        }
        __syncthreads();

        const __half* base = sh_hs[it & 1];
        const int s0 = it * SC;
        #pragma unroll
        for (int i = 0; i < SC / 4; i++) {
            const int ro = squad * (SC / 4) + i;
            const uint4* hrow = reinterpret_cast<const uint4*>(&base[ro * H_]);
            __half2 accA = __float2half2_rn(0.0f);
            __half2 accB = __float2half2_rn(0.0f);
            #pragma unroll
            for (int c = 0; c < 2; c++) {
                const uint4 hv = hrow[c * 32 + lane];
                const __half2 h0 = *reinterpret_cast<const __half2*>(&hv.x);
                const __half2 h1 = *reinterpret_cast<const __half2*>(&hv.y);
                const __half2 h2 = *reinterpret_cast<const __half2*>(&hv.z);
                const __half2 h3 = *reinterpret_cast<const __half2*>(&hv.w);
                accA = __hfma2(tanh2(__hadd2(qh[c * 4 + 0], h0)), vh[c * 4 + 0], accA);
                accB = __hfma2(tanh2(__hadd2(qh[c * 4 + 1], h1)), vh[c * 4 + 1], accB);
                accA = __hfma2(tanh2(__hadd2(qh[c * 4 + 2], h2)), vh[c * 4 + 2], accA);
                accB = __hfma2(tanh2(__hadd2(qh[c * 4 + 3], h3)), vh[c * 4 + 3], accB);
            }
            const float2 fA = __half22float2(accA);
            const float2 fB = __half22float2(accB);
            float acc = (fA.x + fA.y) + (fB.x + fB.y);
            acc += __shfl_xor_sync(0xffffffffu, acc, 16);
            acc += __shfl_xor_sync(0xffffffffu, acc, 8);
            acc += __shfl_xor_sync(0xffffffffu, acc, 4);
            acc += __shfl_xor_sync(0xffffffffu, acc, 2);
            acc += __shfl_xor_sync(0xffffffffu, acc, 1);
            if (lane == 0) sh_sc[s0 + ro][t_loc] = acc;
        }

        if (it + 1 < nch) {
            uint4* dst = reinterpret_cast<uint4*>(&sh_hs[(it + 1) & 1][0]);
            #pragma unroll
            for (int q = 0; q < 2; q++)
                dst[q * 512 + tid] = r[q];
        }
    }
    __syncthreads();

    if (wid < TT) {
        const int t = wid;
        float vals[S_ / 32];
        float m = -1e30f;
        #pragma unroll
        for (int i = 0; i < S_ / 32; i++) {
            const int s = lane + 32 * i;
            const float sc = (s < len) ? sh_sc[s][t] : -1e30f;
            vals[i] = sc;
            m = fmaxf(m, sc);
        }
        #pragma unroll
        for (int o = 16; o; o >>= 1) m = fmaxf(m, __shfl_xor_sync(0xffffffffu, m, o));
        float sum = 0.f;
        #pragma unroll
        for (int i = 0; i < S_ / 32; i++) {
            const int s = lane + 32 * i;
            const float e = (s < len) ? __expf(vals[i] - m) : 0.f;
            sh_sc[s][t] = e;
            sum += e;
        }
        #pragma unroll
        for (int o = 16; o; o >>= 1) sum += __shfl_xor_sync(0xffffffffu, sum, o);
        if (lane == 0) sh_rsum[t] = 1.0f / sum;
    }
    __syncthreads();

    const int g  = tid >> 7;
    const int c4 = tid & 127;
    const int sbeg = (g * len) >> 2;
    const int send = ((g + 1) * len) >> 2;

    float4 acc4[TT];
    #pragma unroll
    for (int t = 0; t < TT; t++) acc4[t] = make_float4(0.f, 0.f, 0.f, 0.f);

    #pragma unroll 4
    for (int s = sbeg; s < send; s++) {
        const float4 e4 = *reinterpret_cast<const float4*>(&encb[(size_t)s * H_ + c4 * 4]);
        const float4 w4 = *reinterpret_cast<const float4*>(&sh_sc[s][0]);
        acc4[0].x = fmaf(w4.x, e4.x, acc4[0].x);
        acc4[0].y = fmaf(w4.x, e4.y, acc4[0].y);
        acc4[0].z = fmaf(w4.x, e4.z, acc4[0].z);
        acc4[0].w = fmaf(w4.x, e4.w, acc4[0].w);
        acc4[1].x = fmaf(w4.y, e4.x, acc4[1].x);
        acc4[1].y = fmaf(w4.y, e4.y, acc4[1].y);
        acc4[1].z = fmaf(w4.y, e4.z, acc4[1].z);
        acc4[1].w = fmaf(w4.y, e4.w, acc4[1].w);
        acc4[2].x = fmaf(w4.z, e4.x, acc4[2].x);
        acc4[2].y = fmaf(w4.z, e4.y, acc4[2].y);
        acc4[2].z = fmaf(w4.z, e4.z, acc4[2].z);
        acc4[2].w = fmaf(w4.z, e4.w, acc4[2].w);
        acc4[3].x = fmaf(w4.w, e4.x, acc4[3].x);
        acc4[3].y = fmaf(w4.w, e4.y, acc4[3].y);
        acc4[3].z = fmaf(w4.w, e4.z, acc4[3].z);
        acc4[3].w = fmaf(w4.w, e4.w, acc4[3].w);
    }

    float* bufA = reinterpret_cast<float*>(&sh_hs[0][0]);
    float* bufB = reinterpret_cast<float*>(&sh_hs[1][0]);
    if (g == 1) {
        #pragma unroll
        for (int t = 0; t < TT; t++)
            *reinterpret_cast<float4*>(&bufA[(t * 128 + c4) * 4]) = acc4[t];
    }
    if (g == 3) {
        #pragma unroll
        for (int t = 0; t < TT; t++)
            *reinterpret_cast<float4*>(&bufB[(t * 128 + c4) * 4]) = acc4[t];
    }
    __syncthreads();
    if (g == 0) {
        #pragma unroll
        for (int t = 0; t < TT; t++) {
            const float4 p = *reinterpret_cast<const float4*>(&bufA[(t * 128 + c4) * 4]);
            acc4[t].x += p.x; acc4[t].y += p.y; acc4[t].z += p.z; acc4[t].w += p.w;
        }
    }
    if (g == 2) {
        #pragma unroll
        for (int t = 0; t < TT; t++) {
            const float4 p = *reinterpret_cast<const float4*>(&bufB[(t * 128 + c4) * 4]);
            acc4[t].x += p.x; acc4[t].y += p.y; acc4[t].z += p.z; acc4[t].w += p.w;
            *reinterpret_cast<float4*>(&bufB[(t * 128 + c4) * 4]) = acc4[t];
        }
    }
    __syncthreads();
    if (g == 0) {
        #pragma unroll
        for (int t = 0; t < TT; t++) {
            const float4 p = *reinterpret_cast<const float4*>(&bufB[(t * 128 + c4) * 4]);
            const float rs = sh_rsum[t];
            const size_t off = (size_t)(b * T_ + t0 + t) * H_ + c4 * 4;
            *reinterpret_cast<uint2*>(&g_cf16[off]) =
                pack_f16x4((acc4[t].x + p.x) * rs, (acc4[t].y + p.y) * rs,
                           (acc4[t].z + p.z) * rs, (acc4[t].w + p.w) * rs);
        }
    }
}

// ---------------------------------------------------------------------------
extern "C" void kernel_launch(void* const* d_in, const int* in_sizes, int n_in,
                              void* d_out, int out_size)
{
    const float* query = (const float*)d_in[0];
    const float* enc   = (const float*)d_in[1];
    const int*   lens  = (const int*)d_in[2];
    const float* W_s   = (const float*)d_in[3];
    const float* W_h   = (const float*)d_in[4];
    const float* v     = (const float*)d_in[5];
    const float* W_out = (const float*)d_in[6];
    const float* b_out = (const float*)d_in[7];
    float* out = (float*)d_out;

    convert_kernel<<<2560, 256>>>(query, enc, W_s, W_h, W_out);
    proj_f16<<<dim3(8, 48), 256>>>();
    attn_kernel<<<dim3(T_ / TT, B_), 512>>>(enc, v, lens);
    out_f16<<<dim3(8, 16, 4), 256>>>();
    oreduce_kernel<<<512, 256>>>(b_out, out);
}